// round 1
// baseline (speedup 1.0000x reference)
#include <cuda_runtime.h>

// Problem constants
#define NB   128
#define NQ   36
#define NN   36
#define IND  1024
#define NKER 8
#define OUTK 128
#define OUTD 1024
#define BQ   (NB * NQ)          // 4608

typedef unsigned long long ull;

// Scratch for agg (B,K, 8, 1024) fp32 = 151 MB. __device__ global: allowed
// (no runtime alloc), allocated at module load.
__device__ __align__(16) float g_agg[(size_t)BQ * NKER * IND];

// ---------------------------------------------------------------------------
// Packed fp32x2 helpers (sm_100+ PTX; ptxas won't auto-fuse these from C++)
// ---------------------------------------------------------------------------
__device__ __forceinline__ void fma2(ull& d, ull a, ull b) {
    asm("fma.rn.f32x2 %0, %1, %2, %0;" : "+l"(d) : "l"(a), "l"(b));
}
__device__ __forceinline__ ull pack2(float x) {
    ull r;
    asm("mov.b64 %0, {%1, %1};" : "=l"(r) : "r"(__float_as_uint(x)));
    return r;
}

// ---------------------------------------------------------------------------
// Kernel 1: gaussian weights + weighted aggregation over neighbourhood.
// One block per (b,q). 128 threads, each owns 8 consecutive d-columns and
// all 8 kernels: acc[8 kernels][4 f32x2-pairs].
// Streams feats (679 MB) exactly once -> HBM-bound.
// ---------------------------------------------------------------------------
__global__ void __launch_bounds__(128) k_agg(
    const float* __restrict__ feats, const float* __restrict__ coords,
    const float* __restrict__ mrho,  const float* __restrict__ mtheta,
    const float* __restrict__ prho,  const float* __restrict__ ptheta)
{
    __shared__ ull w2s[NN][NKER];   // weight broadcast pairs (w,w)

    const int bq  = blockIdx.x;
    const int tid = threadIdx.x;

    if (tid < NN) {
        const float rho = coords[((size_t)bq * NN + tid) * 2 + 0];
        const float th  = coords[((size_t)bq * NN + tid) * 2 + 1];
        float w[NKER];
        float s = 0.0f;
        const float TWO_PI = 6.283185307179586f;
#pragma unroll
        for (int k = 0; k < NKER; k++) {
            const float dr = rho - __ldg(&mrho[k]);
            const float pr = __ldg(&prho[k]);
            const float wr = expf(-0.5f * dr * dr / (1e-14f + pr * pr));
            const float fa = fabsf(th - __ldg(&mtheta[k]));
            const float sa = fabsf(TWO_PI - fa);
            const float an = fminf(fa, sa);
            const float pt = __ldg(&ptheta[k]);
            const float wt = expf(-0.5f * an * an / (1e-14f + pt * pt));
            float wv = wr * wt;
            wv = isnan(wv) ? 0.0f : wv;
            w[k] = wv;
            s += wv;
        }
#pragma unroll
        for (int k = 0; k < NKER; k++)
            w2s[tid][k] = pack2(w[k] / s);
    }
    __syncthreads();

    ull acc[NKER][4];
#pragma unroll
    for (int k = 0; k < NKER; k++)
#pragma unroll
        for (int j = 0; j < 4; j++) acc[k][j] = 0ULL;

    // thread owns floats [tid*8, tid*8+8) of each 1024-wide row
    const ulonglong2* p = reinterpret_cast<const ulonglong2*>(feats)
                        + (size_t)bq * (NN * IND / 4) + tid * 2;

#pragma unroll 2
    for (int n = 0; n < NN; n++) {
        const ulonglong2 f0 = __ldcs(&p[0]);   // streaming: no reuse
        const ulonglong2 f1 = __ldcs(&p[1]);
        p += IND / 4;
        const ull f[4] = {f0.x, f0.y, f1.x, f1.y};
#pragma unroll
        for (int k = 0; k < NKER; k++) {
            const ull wk = w2s[n][k];
            fma2(acc[k][0], f[0], wk);
            fma2(acc[k][1], f[1], wk);
            fma2(acc[k][2], f[2], wk);
            fma2(acc[k][3], f[3], wk);
        }
    }

    float* ob = g_agg + (size_t)bq * (NKER * IND) + tid * 8;
#pragma unroll
    for (int k = 0; k < NKER; k++) {
        ulonglong2 v0; v0.x = acc[k][0]; v0.y = acc[k][1];
        ulonglong2 v1; v1.x = acc[k][2]; v1.y = acc[k][3];
        *reinterpret_cast<ulonglong2*>(ob + (size_t)k * IND)     = v0;
        *reinterpret_cast<ulonglong2*>(ob + (size_t)k * IND + 4) = v1;
    }
}

// ---------------------------------------------------------------------------
// Kernel 2: out[bq, k*128+o] = sum_d agg[bq,k,d] * conv_w[k,d,o]
// 8 batched GEMMs, M=4608 N=128 K=1024. Block tile 128x128x16, 256 threads,
// 8x8 thread tile, f32x2 packed FMAs, register-staged global prefetch.
// ---------------------------------------------------------------------------
#define BM  128
#define BN  128
#define BKK 16

__global__ void __launch_bounds__(256, 2) k_gemm(
    const float* __restrict__ convw, float* __restrict__ out)
{
    __shared__ float As[BKK][BM];   // transposed A tile
    __shared__ float Bs[BKK][BN];

    const int kker = blockIdx.y;
    const int m0   = blockIdx.x * BM;
    const int tid  = threadIdx.x;

    const int tx = tid & 15;          // output col group (8 cols)
    const int ty = tid >> 4;          // output row group (8 rows)

    const int arow = tid >> 2;        // 0..63
    const int acol = (tid & 3) * 4;   // 0,4,8,12
    const int brow = tid >> 5;        // 0..7
    const int bcol = (tid & 31) * 4;  // 0..124

    const size_t ASTRIDE = (size_t)NKER * IND;   // 8192 floats between rows

    const float* Aptr  = g_agg + (size_t)(m0 + arow) * ASTRIDE
                       + (size_t)kker * IND + acol;
    const float* Aptr2 = Aptr + 64 * ASTRIDE;
    const float* Bptr  = convw + (size_t)kker * IND * OUTK
                       + (size_t)brow * OUTK + bcol;

    ull acc[8][4];
#pragma unroll
    for (int i = 0; i < 8; i++)
#pragma unroll
        for (int j = 0; j < 4; j++) acc[i][j] = 0ULL;

    // prologue: stage tile 0
    float4 ra0 = __ldg(reinterpret_cast<const float4*>(Aptr));
    float4 ra1 = __ldg(reinterpret_cast<const float4*>(Aptr2));
    float4 rb0 = __ldg(reinterpret_cast<const float4*>(Bptr));
    float4 rb1 = __ldg(reinterpret_cast<const float4*>(Bptr + 8 * OUTK));

    const int NT = IND / BKK;   // 64 k-tiles
    for (int t = 0; t < NT; t++) {
        // commit staged regs to smem (A transposed)
        As[acol + 0][arow]      = ra0.x;
        As[acol + 1][arow]      = ra0.y;
        As[acol + 2][arow]      = ra0.z;
        As[acol + 3][arow]      = ra0.w;
        As[acol + 0][arow + 64] = ra1.x;
        As[acol + 1][arow + 64] = ra1.y;
        As[acol + 2][arow + 64] = ra1.z;
        As[acol + 3][arow + 64] = ra1.w;
        *reinterpret_cast<float4*>(&Bs[brow][bcol])     = rb0;
        *reinterpret_cast<float4*>(&Bs[brow + 8][bcol]) = rb1;
        __syncthreads();

        if (t < NT - 1) {
            Aptr  += BKK;
            Aptr2 += BKK;
            Bptr  += BKK * OUTK;
            ra0 = __ldg(reinterpret_cast<const float4*>(Aptr));
            ra1 = __ldg(reinterpret_cast<const float4*>(Aptr2));
            rb0 = __ldg(reinterpret_cast<const float4*>(Bptr));
            rb1 = __ldg(reinterpret_cast<const float4*>(Bptr + 8 * OUTK));
        }

#pragma unroll
        for (int kk = 0; kk < BKK; kk++) {
            const float4 a0 = *reinterpret_cast<const float4*>(&As[kk][ty * 8]);
            const float4 a1 = *reinterpret_cast<const float4*>(&As[kk][ty * 8 + 4]);
            const ulonglong2 b0 = *reinterpret_cast<const ulonglong2*>(&Bs[kk][tx * 8]);
            const ulonglong2 b1 = *reinterpret_cast<const ulonglong2*>(&Bs[kk][tx * 8 + 4]);
            const ull bb[4] = {b0.x, b0.y, b1.x, b1.y};
            const float av[8] = {a0.x, a0.y, a0.z, a0.w, a1.x, a1.y, a1.z, a1.w};
#pragma unroll
            for (int i = 0; i < 8; i++) {
                const ull aa = pack2(av[i]);
                fma2(acc[i][0], aa, bb[0]);
                fma2(acc[i][1], aa, bb[1]);
                fma2(acc[i][2], aa, bb[2]);
                fma2(acc[i][3], aa, bb[3]);
            }
        }
        __syncthreads();
    }

    // epilogue: out row = m0 + ty*8 + i, col = kker*128 + tx*8 + j
    float* ob = out + (size_t)(m0 + ty * 8) * OUTD + (size_t)kker * OUTK + tx * 8;
#pragma unroll
    for (int i = 0; i < 8; i++) {
        ulonglong2 v0; v0.x = acc[i][0]; v0.y = acc[i][1];
        ulonglong2 v1; v1.x = acc[i][2]; v1.y = acc[i][3];
        *reinterpret_cast<ulonglong2*>(ob + (size_t)i * OUTD)     = v0;
        *reinterpret_cast<ulonglong2*>(ob + (size_t)i * OUTD + 4) = v1;
    }
}

// ---------------------------------------------------------------------------
extern "C" void kernel_launch(void* const* d_in, const int* in_sizes, int n_in,
                              void* d_out, int out_size)
{
    const float* feats  = (const float*)d_in[0];
    const float* coords = (const float*)d_in[1];
    const float* mrho   = (const float*)d_in[2];
    const float* mtheta = (const float*)d_in[3];
    const float* prho   = (const float*)d_in[4];
    const float* ptheta = (const float*)d_in[5];
    const float* convw  = (const float*)d_in[6];
    float* out = (float*)d_out;

    k_agg<<<BQ, 128>>>(feats, coords, mrho, mtheta, prho, ptheta);

    dim3 g(BQ / BM, NKER);   // (36, 8)
    k_gemm<<<g, 256>>>(convw, out);
}

// round 3
// speedup vs baseline: 1.6969x; 1.6969x over previous
#include <cuda_runtime.h>
#include <cuda_bf16.h>
#include <cstdint>

// ---------------------------------------------------------------------------
// Problem constants
// ---------------------------------------------------------------------------
#define NB    128
#define NQ    36
#define NN    36
#define IND   1024
#define NKER  8
#define OUTK  128
#define OUTD  1024
#define BQ    (NB * NQ)          // 4608
#define MT    36                 // M row-tiles of 128
#define CHUNKS 32                // K chunks of 32 over IND=1024
#define TILE_B 8192              // one tile: 128 rows x 32 bf16 x 2B

typedef unsigned long long ull;

// ---------------------------------------------------------------------------
// Device-global scratch. A (agg) and B (conv_w^T) stored as bf16 hi/lo in a
// pre-swizzled tile format: tile = 128 rows x 32 cols bf16, rows of 64B,
// 16B groups XOR-swizzled by ((row>>1)&3)  -> conflict-free ldmatrix.
// A layout: [kker][mt(36)][chunk(32)] x tile;  B: [kker][chunk(32)] x tile.
// ---------------------------------------------------------------------------
__device__ __align__(128) __nv_bfloat16 g_a_hi[(size_t)NKER * MT * CHUNKS * (TILE_B / 2)];
__device__ __align__(128) __nv_bfloat16 g_a_lo[(size_t)NKER * MT * CHUNKS * (TILE_B / 2)];
__device__ __align__(128) __nv_bfloat16 g_b_hi[(size_t)NKER * CHUNKS * (TILE_B / 2)];
__device__ __align__(128) __nv_bfloat16 g_b_lo[(size_t)NKER * CHUNKS * (TILE_B / 2)];

// ---------------------------------------------------------------------------
// PTX helpers (all non-"a" features: valid on plain sm_103 target)
// ---------------------------------------------------------------------------
__device__ __forceinline__ void fma2(ull& d, ull a, ull b) {
    asm("fma.rn.f32x2 %0, %1, %2, %0;" : "+l"(d) : "l"(a), "l"(b));
}
__device__ __forceinline__ ull pack2(float x) {
    ull r;
    asm("mov.b64 %0, {%1, %1};" : "=l"(r) : "r"(__float_as_uint(x)));
    return r;
}
__device__ __forceinline__ uint32_t smem_u32(const void* p) {
    uint32_t a;
    asm("{ .reg .u64 t; cvta.to.shared.u64 t, %1; cvt.u32.u64 %0, t; }" : "=r"(a) : "l"(p));
    return a;
}
__device__ __forceinline__ void cp16(uint32_t d, const void* s) {
    asm volatile("cp.async.cg.shared.global [%0], [%1], 16;" :: "r"(d), "l"(s));
}
__device__ __forceinline__ void ldx4(uint32_t* r, uint32_t addr) {
    asm volatile("ldmatrix.sync.aligned.m8n8.x4.shared.b16 {%0,%1,%2,%3}, [%4];"
                 : "=r"(r[0]), "=r"(r[1]), "=r"(r[2]), "=r"(r[3]) : "r"(addr));
}
__device__ __forceinline__ void mma16816(float* d, const uint32_t* a, const uint32_t* b) {
    asm volatile(
        "mma.sync.aligned.m16n8k16.row.col.f32.bf16.bf16.f32 "
        "{%0,%1,%2,%3}, {%4,%5,%6,%7}, {%8,%9}, {%0,%1,%2,%3};"
        : "+f"(d[0]), "+f"(d[1]), "+f"(d[2]), "+f"(d[3])
        : "r"(a[0]), "r"(a[1]), "r"(a[2]), "r"(a[3]), "r"(b[0]), "r"(b[1]));
}

// ---------------------------------------------------------------------------
// Kernel 1: gaussian weights + weighted aggregation over neighbourhood.
// One block per (b,q), 256 threads, thread owns 4 consecutive d-cols for all
// 8 kernels. Emits bf16 hi/lo directly in the swizzled GEMM tile layout.
// ---------------------------------------------------------------------------
__global__ void __launch_bounds__(256) k_agg(
    const float* __restrict__ feats, const float* __restrict__ coords,
    const float* __restrict__ mrho,  const float* __restrict__ mtheta,
    const float* __restrict__ prho,  const float* __restrict__ ptheta)
{
    __shared__ ull w2s[NN][NKER];

    const int bq  = blockIdx.x;
    const int tid = threadIdx.x;

    if (tid < NN) {
        const float rho = coords[((size_t)bq * NN + tid) * 2 + 0];
        const float th  = coords[((size_t)bq * NN + tid) * 2 + 1];
        float w[NKER];
        float s = 0.0f;
        const float TWO_PI = 6.283185307179586f;
#pragma unroll
        for (int k = 0; k < NKER; k++) {
            const float dr = rho - __ldg(&mrho[k]);
            const float pr = __ldg(&prho[k]);
            const float wr = expf(-0.5f * dr * dr / (1e-14f + pr * pr));
            const float fa = fabsf(th - __ldg(&mtheta[k]));
            const float sa = fabsf(TWO_PI - fa);
            const float an = fminf(fa, sa);
            const float pt = __ldg(&ptheta[k]);
            const float wt = expf(-0.5f * an * an / (1e-14f + pt * pt));
            float wv = wr * wt;
            wv = isnan(wv) ? 0.0f : wv;
            w[k] = wv;
            s += wv;
        }
#pragma unroll
        for (int k = 0; k < NKER; k++)
            w2s[tid][k] = pack2(w[k] / s);
    }
    __syncthreads();

    ull acc[NKER][2];
#pragma unroll
    for (int k = 0; k < NKER; k++) { acc[k][0] = 0ULL; acc[k][1] = 0ULL; }

    const ulonglong2* p = reinterpret_cast<const ulonglong2*>(feats)
                        + (size_t)bq * (NN * IND / 4) + tid;

#pragma unroll 4
    for (int n = 0; n < NN; n++) {
        const ulonglong2 f = __ldcs(p);
        p += IND / 4;
#pragma unroll
        for (int k = 0; k < NKER; k++) {
            const ull wk = w2s[n][k];
            fma2(acc[k][0], f.x, wk);
            fma2(acc[k][1], f.y, wk);
        }
    }

    // store bf16 hi/lo into swizzled tile layout
    const int row   = bq & 127;
    const int mt128 = bq >> 7;
    const int kc    = tid >> 3;          // chunk index 0..31
    const int g     = (tid >> 1) & 3;    // 16B group within 64B row
    const int half  = tid & 1;           // low/high 8B of group
    const uint32_t sw = (uint32_t)(row * 64 + 16 * (g ^ ((row >> 1) & 3)) + 8 * half);

#pragma unroll
    for (int k = 0; k < NKER; k++) {
        float x0 = __uint_as_float((uint32_t)acc[k][0]);
        float x1 = __uint_as_float((uint32_t)(acc[k][0] >> 32));
        float x2 = __uint_as_float((uint32_t)acc[k][1]);
        float x3 = __uint_as_float((uint32_t)(acc[k][1] >> 32));

        __nv_bfloat16 h0 = __float2bfloat16_rn(x0);
        __nv_bfloat16 h1 = __float2bfloat16_rn(x1);
        __nv_bfloat16 h2 = __float2bfloat16_rn(x2);
        __nv_bfloat16 h3 = __float2bfloat16_rn(x3);
        __nv_bfloat16 l0 = __float2bfloat16_rn(x0 - __bfloat162float(h0));
        __nv_bfloat16 l1 = __float2bfloat16_rn(x1 - __bfloat162float(h1));
        __nv_bfloat16 l2 = __float2bfloat16_rn(x2 - __bfloat162float(h2));
        __nv_bfloat16 l3 = __float2bfloat16_rn(x3 - __bfloat162float(h3));

        union { __nv_bfloat16 h[4]; ull u; } H, L;
        H.h[0] = h0; H.h[1] = h1; H.h[2] = h2; H.h[3] = h3;
        L.h[0] = l0; L.h[1] = l1; L.h[2] = l2; L.h[3] = l3;

        const size_t tile = ((size_t)(k * MT + mt128) * CHUNKS + kc) * TILE_B;
        *reinterpret_cast<ull*>((char*)g_a_hi + tile + sw) = H.u;
        *reinterpret_cast<ull*>((char*)g_a_lo + tile + sw) = L.u;
    }
}

// ---------------------------------------------------------------------------
// Kernel 2: conv_w (k,d,o) -> B^T tiles [kker][chunk] of 128 n-rows x 32 k.
// ---------------------------------------------------------------------------
__global__ void __launch_bounds__(128) k_prep(const float* __restrict__ convw)
{
    __shared__ float s[32 * 128];
    const int kc = blockIdx.x;     // 0..31
    const int kk = blockIdx.y;     // 0..7
    const int tid = threadIdx.x;   // 0..127

    const float4* src = reinterpret_cast<const float4*>(
        convw + (size_t)kk * (IND * OUTK) + (size_t)kc * (32 * OUTK));
    float4* sd = reinterpret_cast<float4*>(s);
#pragma unroll
    for (int i = 0; i < 8; i++)
        sd[tid + i * 128] = __ldg(&src[tid + i * 128]);
    __syncthreads();

    const size_t tbase = ((size_t)kk * CHUNKS + kc) * TILE_B;
    const int n = tid;
    const int swz = (n >> 1) & 3;
#pragma unroll
    for (int g = 0; g < 4; g++) {
        union { __nv_bfloat16 h[8]; uint4 u; } H, L;
#pragma unroll
        for (int j = 0; j < 8; j++) {
            const float v = s[(g * 8 + j) * 128 + n];
            const __nv_bfloat16 h = __float2bfloat16_rn(v);
            H.h[j] = h;
            L.h[j] = __float2bfloat16_rn(v - __bfloat162float(h));
        }
        const uint32_t sw = (uint32_t)(n * 64 + 16 * (g ^ swz));
        *reinterpret_cast<uint4*>((char*)g_b_hi + tbase + sw) = H.u;
        *reinterpret_cast<uint4*>((char*)g_b_lo + tbase + sw) = L.u;
    }
}

// ---------------------------------------------------------------------------
// Kernel 3: HMMA GEMM, bf16x3 split (hi*hi + hi*lo + lo*hi).
// Block 128x128, 8 warps (warp tile 64x32), 3-stage cp.async pipeline,
// K-chunk 32. grid (36, 8), 96KB dynamic smem -> 2 blocks/SM, one wave.
// ---------------------------------------------------------------------------
#define NST 3
#define STAGE_B 32768   // Ah 8K | Al 8K | Bh 8K | Bl 8K

__global__ void __launch_bounds__(256, 2) k_mma(float* __restrict__ out)
{
    extern __shared__ char dsm[];
    const uint32_t sbase = smem_u32(dsm);

    const int tid  = threadIdx.x;
    const int wid  = tid >> 5;
    const int lane = tid & 31;
    const int mt   = blockIdx.x;   // 0..35
    const int kk   = blockIdx.y;   // 0..7

    const int wm = (wid >> 2) * 64;   // warp M offset (0/64)
    const int wn = (wid & 3) * 32;    // warp N offset (0/32/64/96)

    const char* Abh = (const char*)g_a_hi + (size_t)(kk * MT + mt) * CHUNKS * TILE_B;
    const char* Abl = (const char*)g_a_lo + (size_t)(kk * MT + mt) * CHUNKS * TILE_B;
    const char* Bbh = (const char*)g_b_hi + (size_t)kk * CHUNKS * TILE_B;
    const char* Bbl = (const char*)g_b_lo + (size_t)kk * CHUNKS * TILE_B;

    // ldmatrix per-lane address components
    const int j  = lane >> 3;
    const int rr = lane & 7;
    const int a_row  = wm + ((j & 1) << 3) + rr;   // + 16*i
    const int a_gsel = j >> 1;                     // + 2*s
    const int swzA   = (a_row >> 1) & 3;
    const int b_n    = wn + ((j >> 1) << 3) + rr;  // + 16*p
    const int b_gsel = j & 1;                      // + 2*s
    const int swzB   = (b_n >> 1) & 3;

    float acc[4][4][4];
#pragma unroll
    for (int i = 0; i < 4; i++)
#pragma unroll
        for (int t = 0; t < 4; t++)
#pragma unroll
            for (int r = 0; r < 4; r++) acc[i][t][r] = 0.0f;

    // stage loader: 8 x 16B cp.async per thread
    auto load_chunk = [&](int c, uint32_t sb) {
        const uint32_t o = (uint32_t)(tid * 16);
        const char* ah = Abh + (size_t)c * TILE_B + o;
        const char* al = Abl + (size_t)c * TILE_B + o;
        const char* bh = Bbh + (size_t)c * TILE_B + o;
        const char* bl = Bbl + (size_t)c * TILE_B + o;
        cp16(sb + o,                ah);
        cp16(sb + 4096 + o,         ah + 4096);
        cp16(sb + 8192 + o,         al);
        cp16(sb + 12288 + o,        al + 4096);
        cp16(sb + 16384 + o,        bh);
        cp16(sb + 20480 + o,        bh + 4096);
        cp16(sb + 24576 + o,        bl);
        cp16(sb + 28672 + o,        bl + 4096);
        asm volatile("cp.async.commit_group;");
    };

    load_chunk(0, sbase);
    load_chunk(1, sbase + STAGE_B);

    for (int c = 0; c < CHUNKS; c++) {
        if (c < CHUNKS - 1) {
            asm volatile("cp.async.wait_group %0;" :: "n"(1));
        } else {
            asm volatile("cp.async.wait_group %0;" :: "n"(0));
        }
        __syncthreads();
        if (c + 2 < CHUNKS)
            load_chunk(c + 2, sbase + (uint32_t)((c + 2) % NST) * STAGE_B);

        const uint32_t sb  = sbase + (uint32_t)(c % NST) * STAGE_B;
        const uint32_t ahb = sb;
        const uint32_t alb = sb + 8192;
        const uint32_t bhb = sb + 16384;
        const uint32_t blb = sb + 24576;

#pragma unroll
        for (int s = 0; s < 2; s++) {
            uint32_t bh[8], bl[8];
#pragma unroll
            for (int p = 0; p < 2; p++) {
                const uint32_t boff = (uint32_t)((b_n + 16 * p) * 64
                                    + 16 * ((2 * s + b_gsel) ^ swzB));
                ldx4(&bh[4 * p], bhb + boff);
                ldx4(&bl[4 * p], blb + boff);
            }
#pragma unroll
            for (int i = 0; i < 4; i++) {
                uint32_t ah[4], al[4];
                const uint32_t aoff = (uint32_t)((a_row + 16 * i) * 64
                                    + 16 * ((2 * s + a_gsel) ^ swzA));
                ldx4(ah, ahb + aoff);
                ldx4(al, alb + aoff);
#pragma unroll
                for (int t = 0; t < 4; t++) {
                    mma16816(acc[i][t], ah, &bh[2 * t]);
                    mma16816(acc[i][t], ah, &bl[2 * t]);
                    mma16816(acc[i][t], al, &bh[2 * t]);
                }
            }
        }
    }

    // epilogue
#pragma unroll
    for (int i = 0; i < 4; i++) {
        const int r0 = mt * 128 + wm + 16 * i + (lane >> 2);
#pragma unroll
        for (int t = 0; t < 4; t++) {
            const int cN = kk * OUTK + wn + 8 * t + 2 * (lane & 3);
            float2 v0; v0.x = acc[i][t][0]; v0.y = acc[i][t][1];
            float2 v1; v1.x = acc[i][t][2]; v1.y = acc[i][t][3];
            *reinterpret_cast<float2*>(out + (size_t)r0 * OUTD + cN)       = v0;
            *reinterpret_cast<float2*>(out + (size_t)(r0 + 8) * OUTD + cN) = v1;
        }
    }
}

// ---------------------------------------------------------------------------
extern "C" void kernel_launch(void* const* d_in, const int* in_sizes, int n_in,
                              void* d_out, int out_size)
{
    const float* feats  = (const float*)d_in[0];
    const float* coords = (const float*)d_in[1];
    const float* mrho   = (const float*)d_in[2];
    const float* mtheta = (const float*)d_in[3];
    const float* prho   = (const float*)d_in[4];
    const float* ptheta = (const float*)d_in[5];
    const float* convw  = (const float*)d_in[6];
    float* out = (float*)d_out;

    cudaFuncSetAttribute(k_mma, cudaFuncAttributeMaxDynamicSharedMemorySize,
                         NST * STAGE_B);

    dim3 gp(CHUNKS, NKER);
    k_prep<<<gp, 128>>>(convw);
    k_agg<<<BQ, 256>>>(feats, coords, mrho, mtheta, prho, ptheta);
    dim3 gg(MT, NKER);
    k_mma<<<gg, 256, NST * STAGE_B>>>(out);
}